// round 8
// baseline (speedup 1.0000x reference)
#include <cuda_runtime.h>
#include <cstdint>

namespace {

constexpr int B_ = 32768, A_ = 32, D_ = 64, H_ = 128, K_ = 128;
constexpr int RC = 128;              // rows per chunk (k1c, k2)
constexpr int NCH = B_ / RC;         // 256 chunks
constexpr int NPAIR = A_ / 2;        // 16 action pairs

using u64 = unsigned long long;

// K2 dynamic smem (floats): ctx[128*128] + hctx[128*128] + red[128*9]
constexpr int K2_CTX = 0;
constexpr int K2_HCT = RC * K_;
constexpr int K2_RED = 2 * RC * K_;
constexpr int K2_SMEM_BYTES = (2 * RC * K_ + RC * 9) * 4;   // 135680

__device__ __forceinline__ void ffma2(u64& d, u64 a, u64 b) {
  asm("fma.rn.f32x2 %0, %1, %2, %0;" : "+l"(d) : "l"(a), "l"(b));
}
__device__ __forceinline__ u64 fadd2(u64 a, u64 b) {
  u64 r; asm("add.rn.f32x2 %0, %1, %2;" : "=l"(r) : "l"(a), "l"(b)); return r;
}
__device__ __forceinline__ u64 pack2(float a, float b) {
  u64 r; asm("mov.b64 %0, {%1, %2};" : "=l"(r) : "f"(a), "f"(b)); return r;
}
__device__ __forceinline__ void unpack2(u64 v, float& lo, float& hi) {
  asm("mov.b64 {%0, %1}, %2;" : "=f"(lo), "=f"(hi) : "l"(v));
}
// monotonic float -> uint key (increasing)
__device__ __forceinline__ uint32_t fkey(float f) {
  uint32_t u = __float_as_uint(f);
  return (u & 0x80000000u) ? ~u : (u | 0x80000000u);
}

}  // namespace

// -------- device scratch (no runtime alloc) --------
__device__ float g_weff[A_ * K_ * D_];        // [a][k][d]
__device__ float g_beff[A_ * D_];             // [a][d]
__device__ u64   g_wz[A_ * 64 * H_];          // [a][kp][h] packed (k even, k odd)
__device__ float g_c2[A_ * H_];               // [a][h]
__device__ float g_hctx[(size_t)B_ * H_];     // [b][h]  (includes br1)
__device__ u64   g_best[B_];                  // packed (key<<32 | action)
__device__ int   g_bcnt[A_];
__device__ int   g_bucket[A_ * B_];

// ---------------------------------------------------------------------------
// K1a: Weff[a][k][d] = sum_h W2[a][d][h]*W1[a][h][k];  beff
// ---------------------------------------------------------------------------
__global__ void __launch_bounds__(256)
k1a_weff(const float* __restrict__ W1, const float* __restrict__ b1,
         const float* __restrict__ W2, const float* __restrict__ b2) {
  __shared__ float w1s[H_][K_];
  __shared__ float w2s[D_][H_];
  const int a = blockIdx.x, tid = threadIdx.x;
  const float* W1a = W1 + (size_t)a * H_ * K_;
  const float* W2a = W2 + (size_t)a * D_ * H_;
  for (int i = tid; i < H_ * K_ / 4; i += 256)
    reinterpret_cast<float4*>(&w1s[0][0])[i] = reinterpret_cast<const float4*>(W1a)[i];
  for (int i = tid; i < D_ * H_ / 4; i += 256)
    reinterpret_cast<float4*>(&w2s[0][0])[i] = reinterpret_cast<const float4*>(W2a)[i];
  __syncthreads();

  const int k0 = (tid & 31) * 4, d0 = (tid >> 5) * 8;
  float acc[4][8];
#pragma unroll
  for (int i = 0; i < 4; i++)
#pragma unroll
    for (int j = 0; j < 8; j++) acc[i][j] = 0.f;
  for (int h = 0; h < H_; h++) {
    float4 w1v = *reinterpret_cast<const float4*>(&w1s[h][k0]);
    float w1x[4] = {w1v.x, w1v.y, w1v.z, w1v.w};
#pragma unroll
    for (int j = 0; j < 8; j++) {
      float w2v = w2s[d0 + j][h];
#pragma unroll
      for (int i = 0; i < 4; i++) acc[i][j] = fmaf(w2v, w1x[i], acc[i][j]);
    }
  }
  float* dst = g_weff + (size_t)a * K_ * D_;
#pragma unroll
  for (int i = 0; i < 4; i++)
#pragma unroll
    for (int j = 0; j < 8; j++) dst[(k0 + i) * D_ + d0 + j] = acc[i][j];

  if (tid < D_) {
    float s = b2[a * D_ + tid];
    for (int h = 0; h < H_; h++) s = fmaf(w2s[tid][h], b1[a * H_ + h], s);
    g_beff[a * D_ + tid] = s;
  }
}

// ---------------------------------------------------------------------------
// K1b: Wz[a][k][h] = sum_d Weff[a][k][d] * Wp[h][d]  (packed u64 along k)
//      c2[a][h]    = sum_d beff[a][d] * Wp[h][d]
// ---------------------------------------------------------------------------
__global__ void __launch_bounds__(256)
k1b_wz(const float* __restrict__ Wr1) {
  __shared__ float weffs[K_ * D_];   // [k][d]
  __shared__ float wps[H_ * 65];     // [h][d] padded
  const int a = blockIdx.x, tid = threadIdx.x;

  for (int i = tid; i < K_ * D_ / 4; i += 256)
    reinterpret_cast<float4*>(weffs)[i] =
        reinterpret_cast<const float4*>(g_weff + (size_t)a * K_ * D_)[i];
  for (int i = tid; i < H_ * D_ / 4; i += 256) {
    int n = i >> 4, q = i & 15;
    float4 v = *reinterpret_cast<const float4*>(&Wr1[n * 192 + 128 + q * 4]);
    wps[n * 65 + q * 4 + 0] = v.x;
    wps[n * 65 + q * 4 + 1] = v.y;
    wps[n * 65 + q * 4 + 2] = v.z;
    wps[n * 65 + q * 4 + 3] = v.w;
  }
  __syncthreads();

  const int h = tid & 127, khalf = tid >> 7;
  float prev = 0.f;
  for (int k = khalf * 64; k < khalf * 64 + 64; k++) {
    float s = 0.f;
#pragma unroll 8
    for (int d = 0; d < D_; d++) s = fmaf(weffs[k * D_ + d], wps[h * 65 + d], s);
    if (k & 1)
      g_wz[((size_t)a * 64 + (k >> 1)) * H_ + h] = pack2(prev, s);
    else
      prev = s;
  }
  if (tid < H_) {
    float s = 0.f;
    for (int d = 0; d < D_; d++) s = fmaf(g_beff[a * D_ + d], wps[tid * 65 + d], s);
    g_c2[a * H_ + tid] = s;
  }
}

// ---------------------------------------------------------------------------
// K1c: hctx[b][h] = ctx[b] @ Wc[h] + br1[h]; also wemb copy, g_best/g_bcnt init.
// Register-stationary Wc column per thread (2 row-parity groups).
// ---------------------------------------------------------------------------
__global__ void __launch_bounds__(256, 1)
k1c_hctx(const int* __restrict__ x, const int* __restrict__ y,
         const float* __restrict__ cemb, const float* __restrict__ wemb,
         const float* __restrict__ Wr1, const float* __restrict__ br1,
         float* __restrict__ out) {
  __shared__ float ctx[RC * K_];   // 64 KB
  const int tid = threadIdx.x;
  const int row0 = blockIdx.x * RC;

  // stage ctx + wemb copy (2 threads per row)
  {
    int rr = tid >> 1, half = tid & 1;
    int gb = row0 + rr;
    int xi = x[gb * 2 + half];
    const float4* s4 = reinterpret_cast<const float4*>(cemb + (size_t)xi * 64);
    float4* d4 = reinterpret_cast<float4*>(&ctx[rr * K_ + half * 64]);
#pragma unroll
    for (int q = 0; q < 16; q++) d4[q] = s4[q];
    int yy = y[gb];
    const float4* w4 = reinterpret_cast<const float4*>(wemb + (size_t)yy * 64 + half * 32);
    float4* o4 = reinterpret_cast<float4*>(&out[(size_t)B_ * 64 + (size_t)gb * 64 + half * 32]);
#pragma unroll
    for (int q = 0; q < 8; q++) o4[q] = w4[q];
  }
  if (tid < RC) g_best[row0 + tid] = ~0ull;
  if (blockIdx.x == 0 && tid < A_) g_bcnt[tid] = 0;

  const int h = tid & 127, g = tid >> 7;
  u64 wc[64];
#pragma unroll
  for (int q = 0; q < 32; q++) {
    float4 v = *reinterpret_cast<const float4*>(&Wr1[h * 192 + q * 4]);
    wc[2 * q]     = pack2(v.x, v.y);
    wc[2 * q + 1] = pack2(v.z, v.w);
  }
  const float brv = br1[h];
  __syncthreads();

  for (int j0 = 0; j0 < 64; j0 += 4) {
    u64 acc[4][2] = {};
#pragma unroll
    for (int kpp = 0; kpp < 32; kpp++) {
#pragma unroll
      for (int i = 0; i < 4; i++) {
        int r = 2 * (j0 + i) + g;
        ulonglong2 c = *reinterpret_cast<const ulonglong2*>(&ctx[r * K_ + kpp * 4]);
        ffma2(acc[i][0], c.x, wc[2 * kpp]);
        ffma2(acc[i][1], c.y, wc[2 * kpp + 1]);
      }
    }
#pragma unroll
    for (int i = 0; i < 4; i++) {
      u64 t = fadd2(acc[i][0], acc[i][1]);
      float lo, hi;
      unpack2(t, lo, hi);
      g_hctx[(size_t)(row0 + 2 * (j0 + i) + g) * H_ + h] = lo + hi + brv;
    }
  }
}

// ---------------------------------------------------------------------------
// K2: z = ctx @ Wz[a] + hctx + c2; reward = sum relu(z)*wr2; cross-block
// argmin via atomicMin on (key<<32 | action).
// Thread = (action of pair, column h); Wz column register-stationary.
// ---------------------------------------------------------------------------
__global__ void __launch_bounds__(256, 1)
k2_z(const int* __restrict__ x, const float* __restrict__ cemb,
     const float* __restrict__ Wr2) {
  extern __shared__ float sm[];
  float* ctx = sm + K2_CTX;
  float* hct = sm + K2_HCT;
  float* red = sm + K2_RED;
  const int tid = threadIdx.x;
  const int pa = blockIdx.x;
  const int row0 = blockIdx.y * RC;
  const int h = tid & 127;
  const int act = 2 * pa + (tid >> 7);
  const int w = tid >> 5, lane = tid & 31;

  // weights into registers (coalesced across h)
  u64 wz[64];
  {
    const u64* src = g_wz + (size_t)act * 64 * H_ + h;
#pragma unroll
    for (int kp = 0; kp < 64; kp++) wz[kp] = src[kp * H_];
  }
  const float c2v = g_c2[act * H_ + h];
  const float wr2v = Wr2[h];

  // stage ctx (2 threads per row) and hctx (contiguous copy)
  {
    int rr = tid >> 1, half = tid & 1;
    int xi = x[(row0 + rr) * 2 + half];
    const float4* s4 = reinterpret_cast<const float4*>(cemb + (size_t)xi * 64);
    float4* d4 = reinterpret_cast<float4*>(&ctx[rr * K_ + half * 64]);
#pragma unroll
    for (int q = 0; q < 16; q++) d4[q] = s4[q];
  }
  {
    const float4* s4 = reinterpret_cast<const float4*>(g_hctx + (size_t)row0 * H_);
    float4* d4 = reinterpret_cast<float4*>(hct);
    for (int i = tid; i < RC * H_ / 4; i += 256) d4[i] = s4[i];
  }
  __syncthreads();

  for (int g4 = 0; g4 < RC; g4 += 4) {
    u64 acc[4][2] = {};
    // prefetched ctx stream
    ulonglong2 c[4];
#pragma unroll
    for (int i = 0; i < 4; i++)
      c[i] = *reinterpret_cast<const ulonglong2*>(&ctx[(g4 + i) * K_]);
#pragma unroll
    for (int kpp = 0; kpp < 32; kpp++) {
      ulonglong2 cn[4];
      if (kpp < 31) {
#pragma unroll
        for (int i = 0; i < 4; i++)
          cn[i] = *reinterpret_cast<const ulonglong2*>(&ctx[(g4 + i) * K_ + (kpp + 1) * 4]);
      }
#pragma unroll
      for (int i = 0; i < 4; i++) {
        ffma2(acc[i][0], c[i].x, wz[2 * kpp]);
        ffma2(acc[i][1], c[i].y, wz[2 * kpp + 1]);
      }
#pragma unroll
      for (int i = 0; i < 4; i++) c[i] = cn[i];
    }
#pragma unroll
    for (int i = 0; i < 4; i++) {
      u64 t = fadd2(acc[i][0], acc[i][1]);
      float lo, hi;
      unpack2(t, lo, hi);
      float z = lo + hi + hct[(g4 + i) * H_ + h] + c2v;
      float v = fmaxf(z, 0.f) * wr2v;
#pragma unroll
      for (int off = 16; off >= 1; off >>= 1)
        v += __shfl_xor_sync(0xffffffffu, v, off);
      if (lane == 0) red[(g4 + i) * 9 + w] = v;
    }
  }
  __syncthreads();

  if (tid < RC) {
    float s0 = red[tid * 9 + 0] + red[tid * 9 + 1] + red[tid * 9 + 2] + red[tid * 9 + 3];
    float s1 = red[tid * 9 + 4] + red[tid * 9 + 5] + red[tid * 9 + 6] + red[tid * 9 + 7];
    u64 kA = ((u64)fkey(s0) << 32) | (unsigned)(2 * pa);
    u64 kB = ((u64)fkey(s1) << 32) | (unsigned)(2 * pa + 1);
    u64 m = kA < kB ? kA : kB;   // equal keys -> smaller action (first-min)
    atomicMin(&g_best[row0 + tid], m);
  }
}

// ---------------------------------------------------------------------------
// K2b: bucket rows by winning action.
// ---------------------------------------------------------------------------
__global__ void __launch_bounds__(256)
k2b_bucket() {
  int b = blockIdx.x * 256 + threadIdx.x;
  if (b < B_) {
    u64 v = g_best[b];
    int a = (int)(v & 0xFFu);
    int slot = atomicAdd(&g_bcnt[a], 1);
    g_bucket[a * B_ + slot] = b;
  }
}

// ---------------------------------------------------------------------------
// K3: winner preds (exact fp32), bucketed by action (32 chunks per action).
// ---------------------------------------------------------------------------
__global__ void __launch_bounds__(256)
k3_preds(const int* __restrict__ x, const float* __restrict__ cemb,
         float* __restrict__ out) {
  __shared__ float weffs[K_ * D_];
  __shared__ float ctxb[8][K_];
  const int a = blockIdx.x >> 5;
  const int chunk = blockIdx.x & 31;
  const int tid = threadIdx.x, wid = tid >> 5, lid = tid & 31;

  for (int i = tid; i < K_ * D_ / 4; i += 256)
    reinterpret_cast<float4*>(weffs)[i] =
        reinterpret_cast<const float4*>(g_weff + (size_t)a * K_ * D_)[i];
  __syncthreads();

  const int cnt = g_bcnt[a];
  const float bf0 = g_beff[a * D_ + 2 * lid];
  const float bf1 = g_beff[a * D_ + 2 * lid + 1];

  for (int ii = wid;; ii += 8) {
    int i = chunk + 32 * ii;
    if (i >= cnt) break;
    int b = g_bucket[a * B_ + i];
    {
      int k0 = lid * 4;
      int xi = x[2 * b + (lid >> 4)];
      float4 v = *reinterpret_cast<const float4*>(cemb + (size_t)xi * 64 + (k0 & 63));
      *reinterpret_cast<float4*>(&ctxb[wid][k0]) = v;
    }
    __syncwarp();
    float s0 = bf0, s1 = bf1;
#pragma unroll 4
    for (int k = 0; k < K_; k++) {
      float c = ctxb[wid][k];
      s0 = fmaf(c, weffs[k * D_ + 2 * lid], s0);
      s1 = fmaf(c, weffs[k * D_ + 2 * lid + 1], s1);
    }
    *reinterpret_cast<float2*>(&out[(size_t)b * 64 + 2 * lid]) = make_float2(s0, s1);
    __syncwarp();
  }
}

extern "C" void kernel_launch(void* const* d_in, const int* in_sizes, int n_in,
                              void* d_out, int out_size) {
  (void)in_sizes; (void)n_in; (void)out_size;
  const int*   x    = (const int*)d_in[0];
  const int*   y    = (const int*)d_in[1];
  const float* cemb = (const float*)d_in[2];
  const float* wemb = (const float*)d_in[3];
  const float* W1   = (const float*)d_in[4];
  const float* b1   = (const float*)d_in[5];
  const float* W2   = (const float*)d_in[6];
  const float* b2   = (const float*)d_in[7];
  const float* Wr1  = (const float*)d_in[8];
  const float* br1  = (const float*)d_in[9];
  const float* Wr2  = (const float*)d_in[10];
  float* out = (float*)d_out;

  cudaFuncSetAttribute(k2_z, cudaFuncAttributeMaxDynamicSharedMemorySize,
                       K2_SMEM_BYTES);

  k1a_weff<<<A_, 256>>>(W1, b1, W2, b2);
  k1b_wz<<<A_, 256>>>(Wr1);
  k1c_hctx<<<NCH, 256>>>(x, y, cemb, wemb, Wr1, br1, out);
  k2_z<<<dim3(NPAIR, NCH), 256, K2_SMEM_BYTES>>>(x, cemb, Wr2);
  k2b_bucket<<<B_ / 256, 256>>>();
  k3_preds<<<A_ * 32, 256>>>(x, cemb, out);
}

// round 9
// speedup vs baseline: 1.6513x; 1.6513x over previous
#include <cuda_runtime.h>
#include <cstdint>

namespace {

constexpr int B_ = 32768, A_ = 32, D_ = 64, H_ = 128, K_ = 128;
constexpr int NCH = 256;     // 128-row chunks
constexpr int GRP = 8;       // action groups of 4

using u64 = unsigned long long;

// kz smem float offsets
constexpr int CTXS   = 132;          // padded ctx row stride (floats)
constexpr int OFF_CTX = 0;           // 128*132 = 16896 f
constexpr int OFF_WZ0 = 16896;       // u64[64][128] = 16384 f
constexpr int OFF_WZ1 = 33280;
constexpr int OFF_RED = 49664;       // 256 f
constexpr int ZSMEM   = 49920 * 4;   // 199680 B
constexpr int HSMEM   = (16896 + 16384) * 4;  // 133120 B

__device__ __forceinline__ void ffma2(u64& d, u64 a, u64 b) {
  asm("fma.rn.f32x2 %0, %1, %2, %0;" : "+l"(d) : "l"(a), "l"(b));
}
__device__ __forceinline__ u64 pack2(float a, float b) {
  u64 r; asm("mov.b64 %0, {%1, %2};" : "=l"(r) : "f"(a), "f"(b)); return r;
}
__device__ __forceinline__ void unpack2(u64 v, float& lo, float& hi) {
  asm("mov.b64 {%0, %1}, %2;" : "=f"(lo), "=f"(hi) : "l"(v));
}
__device__ __forceinline__ uint32_t fkey(float f) {
  uint32_t u = __float_as_uint(f);
  return (u & 0x80000000u) ? ~u : (u | 0x80000000u);
}
__device__ __forceinline__ uint32_t smem_u32(const void* p) {
  uint32_t a;
  asm("{ .reg .u64 t; cvta.to.shared.u64 t, %1; cvt.u32.u64 %0, t; }" : "=r"(a) : "l"(p));
  return a;
}
__device__ __forceinline__ void cp16(uint32_t dst, const void* src) {
  asm volatile("cp.async.cg.shared.global [%0], [%1], 16;" :: "r"(dst), "l"(src));
}
__device__ __forceinline__ void cp_commit() {
  asm volatile("cp.async.commit_group;" ::: "memory");
}
__device__ __forceinline__ void cp_wait0() {
  asm volatile("cp.async.wait_group 0;" ::: "memory");
}

}  // namespace

// -------- device scratch (no runtime alloc) --------
__device__ float g_weff[A_ * K_ * D_];                 // [a][k][d]
__device__ float g_beff[A_ * D_];                      // [a][d]
__device__ __align__(16) u64 g_wz[33 * 64 * H_];       // [t][kp][h]; t=32 is Wc
__device__ float g_c2[33 * H_];                        // [t][h]; t=32 is br1
__device__ __align__(16) float g_ctxp[(size_t)B_ * K_];
__device__ float g_hctx[(size_t)B_ * H_];
__device__ u64   g_best[B_];
__device__ int   g_bcnt[A_];
__device__ int   g_bucket[A_ * B_];

// ---------------------------------------------------------------------------
// Shared GEMM pass: acc[i][j][e] (k-pair-packed u64) for rows R0+rg+8i,
// cols Cb+8j+2cg+e.  x from ctx smem (stride 132), w from wz smem [kp][h].
// ---------------------------------------------------------------------------
__device__ __forceinline__ void gemm_pass(const float* __restrict__ ctxs,
                                          const u64* __restrict__ wzs,
                                          int R0, int Cb, int rg, int cg,
                                          u64 acc[4][4][2]) {
#pragma unroll
  for (int i = 0; i < 4; i++)
#pragma unroll
    for (int j = 0; j < 4; j++) { acc[i][j][0] = 0ull; acc[i][j][1] = 0ull; }

  const float* xb = ctxs + (R0 + rg) * CTXS;
  const u64*   wb = wzs + Cb + 2 * cg;

#pragma unroll 8
  for (int kq = 0; kq < 32; kq++) {
    ulonglong2 xv[4];
#pragma unroll
    for (int i = 0; i < 4; i++)
      xv[i] = *reinterpret_cast<const ulonglong2*>(xb + i * 8 * CTXS + kq * 4);
    ulonglong2 w0[4], w1[4];
#pragma unroll
    for (int j = 0; j < 4; j++) {
      w0[j] = *reinterpret_cast<const ulonglong2*>(wb + (2 * kq + 0) * H_ + 8 * j);
      w1[j] = *reinterpret_cast<const ulonglong2*>(wb + (2 * kq + 1) * H_ + 8 * j);
    }
#pragma unroll
    for (int i = 0; i < 4; i++)
#pragma unroll
      for (int j = 0; j < 4; j++) {
        ffma2(acc[i][j][0], xv[i].x, w0[j].x);
        ffma2(acc[i][j][1], xv[i].x, w0[j].y);
        ffma2(acc[i][j][0], xv[i].y, w1[j].x);
        ffma2(acc[i][j][1], xv[i].y, w1[j].y);
      }
  }
}

// ---------------------------------------------------------------------------
// K1a: Weff[a][k][d] = sum_h W2[a][d][h]*W1[a][h][k];  beff; bcnt reset
// ---------------------------------------------------------------------------
__global__ void __launch_bounds__(256)
k1a_weff(const float* __restrict__ W1, const float* __restrict__ b1,
         const float* __restrict__ W2, const float* __restrict__ b2) {
  __shared__ float w1s[H_][K_];
  __shared__ float w2s[D_][H_];
  const int a = blockIdx.x, tid = threadIdx.x;
  if (a == 0 && tid < A_) g_bcnt[tid] = 0;
  const float* W1a = W1 + (size_t)a * H_ * K_;
  const float* W2a = W2 + (size_t)a * D_ * H_;
  for (int i = tid; i < H_ * K_ / 4; i += 256)
    reinterpret_cast<float4*>(&w1s[0][0])[i] = reinterpret_cast<const float4*>(W1a)[i];
  for (int i = tid; i < D_ * H_ / 4; i += 256)
    reinterpret_cast<float4*>(&w2s[0][0])[i] = reinterpret_cast<const float4*>(W2a)[i];
  __syncthreads();

  const int k0 = (tid & 31) * 4, d0 = (tid >> 5) * 8;
  float acc[4][8];
#pragma unroll
  for (int i = 0; i < 4; i++)
#pragma unroll
    for (int j = 0; j < 8; j++) acc[i][j] = 0.f;
  for (int h = 0; h < H_; h++) {
    float4 w1v = *reinterpret_cast<const float4*>(&w1s[h][k0]);
    float w1x[4] = {w1v.x, w1v.y, w1v.z, w1v.w};
#pragma unroll
    for (int j = 0; j < 8; j++) {
      float w2v = w2s[d0 + j][h];
#pragma unroll
      for (int i = 0; i < 4; i++) acc[i][j] = fmaf(w2v, w1x[i], acc[i][j]);
    }
  }
  float* dst = g_weff + (size_t)a * K_ * D_;
#pragma unroll
  for (int i = 0; i < 4; i++)
#pragma unroll
    for (int j = 0; j < 8; j++) dst[(k0 + i) * D_ + d0 + j] = acc[i][j];

  if (tid < D_) {
    float s = b2[a * D_ + tid];
    for (int h = 0; h < H_; h++) s = fmaf(w2s[tid][h], b1[a * H_ + h], s);
    g_beff[a * D_ + tid] = s;
  }
}

// ---------------------------------------------------------------------------
// K1b: tiles t<32: Wz[t][kp][h] = pack(sum_d Weff[t][2kp][d]*Wp[h][d], odd k),
//      c2[t][h] = beff[t].Wp[h].   Tile 32: Wc (packed) + br1.
// ---------------------------------------------------------------------------
__global__ void __launch_bounds__(256)
k1b_wz(const float* __restrict__ Wr1, const float* __restrict__ br1) {
  const int t = blockIdx.x, tid = threadIdx.x;

  if (t == 32) {
    for (int it = 0; it < 32; it++) {
      int idx = tid + it * 256;
      int kp = idx >> 7, h = idx & 127;
      float2 v = *reinterpret_cast<const float2*>(&Wr1[h * 192 + 2 * kp]);
      g_wz[(size_t)32 * 8192 + kp * H_ + h] = pack2(v.x, v.y);
    }
    if (tid < H_) g_c2[32 * H_ + tid] = br1[tid];
    return;
  }

  __shared__ float weffs[K_ * D_];
  __shared__ float wps[H_ * 65];
  for (int i = tid; i < K_ * D_ / 4; i += 256)
    reinterpret_cast<float4*>(weffs)[i] =
        reinterpret_cast<const float4*>(g_weff + (size_t)t * K_ * D_)[i];
  for (int i = tid; i < H_ * D_ / 4; i += 256) {
    int n = i >> 4, q = i & 15;
    float4 v = *reinterpret_cast<const float4*>(&Wr1[n * 192 + 128 + q * 4]);
    wps[n * 65 + q * 4 + 0] = v.x;
    wps[n * 65 + q * 4 + 1] = v.y;
    wps[n * 65 + q * 4 + 2] = v.z;
    wps[n * 65 + q * 4 + 3] = v.w;
  }
  __syncthreads();

  const int h = tid & 127, khalf = tid >> 7;
  float prev = 0.f;
  for (int k = khalf * 64; k < khalf * 64 + 64; k++) {
    float s = 0.f;
#pragma unroll 8
    for (int d = 0; d < D_; d++) s = fmaf(weffs[k * D_ + d], wps[h * 65 + d], s);
    if (k & 1)
      g_wz[(size_t)t * 8192 + (k >> 1) * H_ + h] = pack2(prev, s);
    else
      prev = s;
  }
  if (tid < H_) {
    float s = 0.f;
    for (int d = 0; d < D_; d++) s = fmaf(g_beff[t * D_ + d], wps[tid * 65 + d], s);
    g_c2[t * H_ + tid] = s;
  }
}

// ---------------------------------------------------------------------------
// Khctx: hctx = ctx @ Wc + br1 -> gmem.  Also: ctx gather -> g_ctxp,
// wemb copy, g_best init.
// ---------------------------------------------------------------------------
__global__ void __launch_bounds__(256, 1)
khctx(const int* __restrict__ x, const int* __restrict__ y,
      const float* __restrict__ cemb, const float* __restrict__ wemb,
      float* __restrict__ out) {
  extern __shared__ float smf[];
  const uint32_t smb = smem_u32(smf);
  const int tid = threadIdx.x;
  const int row0 = blockIdx.x * 128;
  const int wid = tid >> 5, lane = tid & 31;
  const int R0 = (wid >> 1) * 32, C0 = (wid & 1) * 32;
  const int rg = lane >> 2, cg = lane & 3;

  // gather ctx -> smem + g_ctxp; wemb copy
  {
    int row = tid >> 1, half = tid & 1;
    int gb = row0 + row;
    int xi = x[gb * 2 + half];
    const float4* s4 = reinterpret_cast<const float4*>(cemb + (size_t)xi * 64);
#pragma unroll
    for (int q = 0; q < 16; q++) {
      float4 v = s4[q];
      *reinterpret_cast<float4*>(&smf[OFF_CTX + row * CTXS + half * 64 + q * 4]) = v;
      *reinterpret_cast<float4*>(&g_ctxp[(size_t)gb * K_ + half * 64 + q * 4]) = v;
    }
    int yy = y[gb];
    const float4* w4 = reinterpret_cast<const float4*>(wemb + (size_t)yy * 64 + half * 32);
    float4* o4 = reinterpret_cast<float4*>(&out[(size_t)B_ * 64 + (size_t)gb * 64 + half * 32]);
#pragma unroll
    for (int q = 0; q < 8; q++) o4[q] = w4[q];
  }
  if (tid < 128) g_best[row0 + tid] = ~0ull;

  // stage Wc tile
  {
    const u64* src = g_wz + (size_t)32 * 8192;
    for (int it = 0; it < 16; it++) {
      int idx = tid + it * 256;
      cp16(smb + OFF_WZ0 * 4 + idx * 16, src + idx * 2);
    }
    cp_commit(); cp_wait0();
  }
  __syncthreads();

  const u64* wzs = reinterpret_cast<const u64*>(smf + OFF_WZ0);
#pragma unroll 1
  for (int p = 0; p < 2; p++) {
    const int Cb = p * 64 + C0;
    u64 acc[4][4][2];
    gemm_pass(smf + OFF_CTX, wzs, R0, Cb, rg, cg, acc);
#pragma unroll
    for (int j = 0; j < 4; j++) {
      float2 cc = *reinterpret_cast<const float2*>(&g_c2[32 * H_ + Cb + 8 * j + 2 * cg]);
#pragma unroll
      for (int i = 0; i < 4; i++) {
        float e0, o0, e1, o1;
        unpack2(acc[i][j][0], e0, o0);
        unpack2(acc[i][j][1], e1, o1);
        size_t rr = (size_t)(row0 + R0 + rg + 8 * i);
        *reinterpret_cast<float2*>(&g_hctx[rr * H_ + Cb + 8 * j + 2 * cg]) =
            make_float2(e0 + o0 + cc.x, e1 + o1 + cc.y);
      }
    }
  }
}

// ---------------------------------------------------------------------------
// Kz: per (chunk, action-group of 4): z = ctx@Wz[a] + hctx + c2; reward;
// argmin via atomicMin(key|action).  Double-buffered wz via cp.async.
// ---------------------------------------------------------------------------
__global__ void __launch_bounds__(256, 1)
kz(const float* __restrict__ Wr2) {
  extern __shared__ float smf[];
  const uint32_t smb = smem_u32(smf);
  const int tid = threadIdx.x;
  const int chunk = blockIdx.x, grp = blockIdx.y;
  const int row0 = chunk * 128;
  const int wid = tid >> 5, lane = tid & 31;
  const int R0 = (wid >> 1) * 32, C0 = (wid & 1) * 32, cb = wid & 1;
  const int rg = lane >> 2, cg = lane & 3;

  // wr2 at this lane's columns (both passes)
  float2 wr2v[2][4];
#pragma unroll
  for (int p = 0; p < 2; p++)
#pragma unroll
    for (int j = 0; j < 4; j++)
      wr2v[p][j] = *reinterpret_cast<const float2*>(&Wr2[p * 64 + C0 + 8 * j + 2 * cg]);

  // stage ctx + wz(a0)
  {
    const float* src = g_ctxp + (size_t)row0 * K_;
    for (int it = 0; it < 16; it++) {
      int idx = tid + it * 256;
      int row = idx >> 5, q = idx & 31;
      cp16(smb + (OFF_CTX + row * CTXS + q * 4) * 4, src + row * K_ + q * 4);
    }
    const u64* wsrc = g_wz + (size_t)(grp * 4) * 8192;
    for (int it = 0; it < 16; it++) {
      int idx = tid + it * 256;
      cp16(smb + OFF_WZ0 * 4 + idx * 16, wsrc + idx * 2);
    }
    cp_commit(); cp_wait0();
  }
  __syncthreads();

#pragma unroll 1
  for (int ai = 0; ai < 4; ai++) {
    const int a = grp * 4 + ai;
    const u64* wzs = reinterpret_cast<const u64*>(smf + ((ai & 1) ? OFF_WZ1 : OFF_WZ0));

    // prefetch next action's wz into the other buffer
    if (ai < 3) {
      const u64* src = g_wz + (size_t)(a + 1) * 8192;
      uint32_t dstb = smb + ((ai & 1) ? OFF_WZ0 : OFF_WZ1) * 4;
      for (int it = 0; it < 16; it++) {
        int idx = tid + it * 256;
        cp16(dstb + idx * 16, src + idx * 2);
      }
      cp_commit();
    }

    float s[4] = {0.f, 0.f, 0.f, 0.f};
#pragma unroll 1
    for (int p = 0; p < 2; p++) {
      const int Cb = p * 64 + C0;
      u64 acc[4][4][2];
      gemm_pass(smf + OFF_CTX, wzs, R0, Cb, rg, cg, acc);
#pragma unroll
      for (int j = 0; j < 4; j++) {
        float2 cc = *reinterpret_cast<const float2*>(&g_c2[a * H_ + Cb + 8 * j + 2 * cg]);
        float2 w2 = wr2v[p][j];
#pragma unroll
        for (int i = 0; i < 4; i++) {
          size_t rr = (size_t)(row0 + R0 + rg + 8 * i);
          float2 hc = *reinterpret_cast<const float2*>(&g_hctx[rr * H_ + Cb + 8 * j + 2 * cg]);
          float e0, o0, e1, o1;
          unpack2(acc[i][j][0], e0, o0);
          unpack2(acc[i][j][1], e1, o1);
          float z0 = e0 + o0 + hc.x + cc.x;
          float z1 = e1 + o1 + hc.y + cc.y;
          s[i] = fmaf(fmaxf(z0, 0.f), w2.x, s[i]);
          s[i] = fmaf(fmaxf(z1, 0.f), w2.y, s[i]);
        }
      }
    }

    // reduce over the 4 colgrp lanes (lane bits 0-1)
#pragma unroll
    for (int i = 0; i < 4; i++) {
      s[i] += __shfl_xor_sync(0xffffffffu, s[i], 1);
      s[i] += __shfl_xor_sync(0xffffffffu, s[i], 2);
    }
    if (cg == 0) {
#pragma unroll
      for (int i = 0; i < 4; i++)
        smf[OFF_RED + (R0 + rg + 8 * i) * 2 + cb] = s[i];
    }
    if (ai < 3) cp_wait0();
    __syncthreads();

    if (tid < 128) {
      float tot = smf[OFF_RED + tid * 2] + smf[OFF_RED + tid * 2 + 1];
      u64 key = ((u64)fkey(tot) << 32) | (unsigned)a;
      atomicMin(&g_best[row0 + tid], key);   // ties -> smaller a = first-min
    }
    __syncthreads();
  }
}

// ---------------------------------------------------------------------------
// K2b: bucket rows by winning action.
// ---------------------------------------------------------------------------
__global__ void __launch_bounds__(256)
k2b_bucket() {
  int b = blockIdx.x * 256 + threadIdx.x;
  if (b < B_) {
    u64 v = g_best[b];
    int a = (int)(v & 0xFFu);
    int slot = atomicAdd(&g_bcnt[a], 1);
    g_bucket[a * B_ + slot] = b;
  }
}

// ---------------------------------------------------------------------------
// K3: winner preds (exact fp32), bucketed by action.
// ---------------------------------------------------------------------------
__global__ void __launch_bounds__(256)
k3_preds(const int* __restrict__ x, const float* __restrict__ cemb,
         float* __restrict__ out) {
  __shared__ float weffs[K_ * D_];
  __shared__ float ctxb[8][K_];
  const int a = blockIdx.x >> 5;
  const int chunk = blockIdx.x & 31;
  const int tid = threadIdx.x, wid = tid >> 5, lid = tid & 31;

  for (int i = tid; i < K_ * D_ / 4; i += 256)
    reinterpret_cast<float4*>(weffs)[i] =
        reinterpret_cast<const float4*>(g_weff + (size_t)a * K_ * D_)[i];
  __syncthreads();

  const int cnt = g_bcnt[a];
  const float bf0 = g_beff[a * D_ + 2 * lid];
  const float bf1 = g_beff[a * D_ + 2 * lid + 1];

  for (int ii = wid;; ii += 8) {
    int i = chunk + 32 * ii;
    if (i >= cnt) break;
    int b = g_bucket[a * B_ + i];
    {
      int k0 = lid * 4;
      int xi = x[2 * b + (lid >> 4)];
      float4 v = *reinterpret_cast<const float4*>(cemb + (size_t)xi * 64 + (k0 & 63));
      *reinterpret_cast<float4*>(&ctxb[wid][k0]) = v;
    }
    __syncwarp();
    float s0 = bf0, s1 = bf1;
#pragma unroll 4
    for (int k = 0; k < K_; k++) {
      float c = ctxb[wid][k];
      s0 = fmaf(c, weffs[k * D_ + 2 * lid], s0);
      s1 = fmaf(c, weffs[k * D_ + 2 * lid + 1], s1);
    }
    *reinterpret_cast<float2*>(&out[(size_t)b * 64 + 2 * lid]) = make_float2(s0, s1);
    __syncwarp();
  }
}

extern "C" void kernel_launch(void* const* d_in, const int* in_sizes, int n_in,
                              void* d_out, int out_size) {
  (void)in_sizes; (void)n_in; (void)out_size;
  const int*   x    = (const int*)d_in[0];
  const int*   y    = (const int*)d_in[1];
  const float* cemb = (const float*)d_in[2];
  const float* wemb = (const float*)d_in[3];
  const float* W1   = (const float*)d_in[4];
  const float* b1   = (const float*)d_in[5];
  const float* W2   = (const float*)d_in[6];
  const float* b2   = (const float*)d_in[7];
  const float* Wr1  = (const float*)d_in[8];
  const float* br1  = (const float*)d_in[9];
  const float* Wr2  = (const float*)d_in[10];
  float* out = (float*)d_out;

  cudaFuncSetAttribute(khctx, cudaFuncAttributeMaxDynamicSharedMemorySize, HSMEM);
  cudaFuncSetAttribute(kz, cudaFuncAttributeMaxDynamicSharedMemorySize, ZSMEM);

  k1a_weff<<<A_, 256>>>(W1, b1, W2, b2);
  k1b_wz<<<33, 256>>>(Wr1, br1);
  khctx<<<NCH, 256, HSMEM>>>(x, y, cemb, wemb, out);
  kz<<<dim3(NCH, GRP), 256, ZSMEM>>>(Wr2);
  k2b_bucket<<<B_ / 256, 256>>>();
  k3_preds<<<A_ * 32, 256>>>(x, cemb, out);
}